// round 1
// baseline (speedup 1.0000x reference)
#include <cuda_runtime.h>
#include <math.h>

#define NH   16
#define DK   64
#define DM   1024
#define NB   2
#define SEQ  2048
#define MTOK (NB * SEQ)   // 4096

// Scratch (device globals — no allocation allowed)
__device__ float g_q[(size_t)MTOK * DM];
__device__ float g_k[(size_t)MTOK * DM];
__device__ float g_v[(size_t)MTOK * DM];
__device__ float g_ctx[(size_t)MTOK * DM];

// ---------------------------------------------------------------------------
// GEMM (NT): C[M,N] = A[M,K] * W[N,K]^T + bias[N]
// BM=128, BN=128, BK=16, 256 threads, 8x8 microtile per thread
// ---------------------------------------------------------------------------
#define BM 128
#define BN 128
#define BK 16

__global__ __launch_bounds__(256) void gemm_nt_bias(
    const float* __restrict__ A, const float* __restrict__ W,
    const float* __restrict__ bias, float* __restrict__ C,
    int M, int N, int K)
{
    __shared__ float As[BK][BM + 4];
    __shared__ float Bs[BK][BN + 4];

    const int tid = threadIdx.x;
    const int bm = blockIdx.y * BM;
    const int bn = blockIdx.x * BN;
    const int tx = tid & 15;   // 0..15 -> 8 cols each
    const int ty = tid >> 4;   // 0..15 -> 8 rows each

    float acc[8][8];
#pragma unroll
    for (int i = 0; i < 8; i++)
#pragma unroll
        for (int j = 0; j < 8; j++) acc[i][j] = 0.0f;

    const int lr = tid >> 2;          // 0..63
    const int lk = (tid & 3) << 2;    // 0,4,8,12

    for (int k0 = 0; k0 < K; k0 += BK) {
#pragma unroll
        for (int r = 0; r < 2; r++) {
            int row = lr + r * 64;
            float4 a4 = *(const float4*)(A + (size_t)(bm + row) * K + k0 + lk);
            As[lk + 0][row] = a4.x;
            As[lk + 1][row] = a4.y;
            As[lk + 2][row] = a4.z;
            As[lk + 3][row] = a4.w;
            float4 b4 = *(const float4*)(W + (size_t)(bn + row) * K + k0 + lk);
            Bs[lk + 0][row] = b4.x;
            Bs[lk + 1][row] = b4.y;
            Bs[lk + 2][row] = b4.z;
            Bs[lk + 3][row] = b4.w;
        }
        __syncthreads();

#pragma unroll
        for (int k = 0; k < BK; k++) {
            float a[8], b[8];
            *(float4*)&a[0] = *(const float4*)&As[k][ty * 8];
            *(float4*)&a[4] = *(const float4*)&As[k][ty * 8 + 4];
            *(float4*)&b[0] = *(const float4*)&Bs[k][tx * 8];
            *(float4*)&b[4] = *(const float4*)&Bs[k][tx * 8 + 4];
#pragma unroll
            for (int i = 0; i < 8; i++)
#pragma unroll
                for (int j = 0; j < 8; j++)
                    acc[i][j] = fmaf(a[i], b[j], acc[i][j]);
        }
        __syncthreads();
    }

#pragma unroll
    for (int i = 0; i < 8; i++) {
        int row = bm + ty * 8 + i;
#pragma unroll
        for (int j = 0; j < 8; j += 4) {
            int col = bn + tx * 8 + j;
            float4 o;
            o.x = acc[i][j + 0] + bias[col + 0];
            o.y = acc[i][j + 1] + bias[col + 1];
            o.z = acc[i][j + 2] + bias[col + 2];
            o.w = acc[i][j + 3] + bias[col + 3];
            *(float4*)(C + (size_t)row * N + col) = o;
        }
    }
}

// ---------------------------------------------------------------------------
// Flash-style attention: one thread = one query row, online softmax.
// grid (SEQ/128, NH, NB), 128 threads.
// Reads g_q/g_k/g_v, writes g_ctx in [b, s, h*DK+d] layout.
// ---------------------------------------------------------------------------
__global__ __launch_bounds__(128) void attn_kernel()
{
    __shared__ float4 ks[64][16];   // 64 keys x 64 dims
    __shared__ float4 vs[64][16];

    const int b = blockIdx.z;
    const int h = blockIdx.y;
    const int row = blockIdx.x * 128 + threadIdx.x;

    const size_t qoff = ((size_t)(b * SEQ + row)) * DM + h * DK;
    const float scale = 0.125f;  // 1/sqrt(64)

    float4 q[16];
#pragma unroll
    for (int i = 0; i < 16; i++) {
        float4 t = *(const float4*)(g_q + qoff + i * 4);
        q[i].x = t.x * scale;
        q[i].y = t.y * scale;
        q[i].z = t.z * scale;
        q[i].w = t.w * scale;
    }

    float o[64];
#pragma unroll
    for (int i = 0; i < 64; i++) o[i] = 0.0f;
    float m = -1e30f, l = 0.0f;

    for (int kv0 = 0; kv0 < SEQ; kv0 += 64) {
        __syncthreads();
        for (int i = threadIdx.x; i < 64 * 16; i += 128) {
            int j  = i >> 4;
            int dq = i & 15;
            size_t g = ((size_t)(b * SEQ + kv0 + j)) * DM + h * DK + dq * 4;
            ks[j][dq] = *(const float4*)(g_k + g);
            vs[j][dq] = *(const float4*)(g_v + g);
        }
        __syncthreads();

#pragma unroll 1
        for (int c0 = 0; c0 < 64; c0 += 16) {
            float s[16];
#pragma unroll
            for (int c = 0; c < 16; c++) {
                float ax = 0.f, ay = 0.f, az = 0.f, aw = 0.f;
#pragma unroll
                for (int i = 0; i < 16; i++) {
                    float4 kk = ks[c0 + c][i];
                    ax = fmaf(q[i].x, kk.x, ax);
                    ay = fmaf(q[i].y, kk.y, ay);
                    az = fmaf(q[i].z, kk.z, az);
                    aw = fmaf(q[i].w, kk.w, aw);
                }
                s[c] = (ax + ay) + (az + aw);
            }

            float mc = s[0];
#pragma unroll
            for (int c = 1; c < 16; c++) mc = fmaxf(mc, s[c]);
            float mnew = fmaxf(m, mc);
            float corr = __expf(m - mnew);
            m = mnew;
            l *= corr;
#pragma unroll
            for (int i = 0; i < 64; i++) o[i] *= corr;

#pragma unroll
            for (int c = 0; c < 16; c++) {
                float p = __expf(s[c] - m);
                l += p;
#pragma unroll
                for (int i = 0; i < 16; i++) {
                    float4 vv = vs[c0 + c][i];
                    o[4 * i + 0] = fmaf(p, vv.x, o[4 * i + 0]);
                    o[4 * i + 1] = fmaf(p, vv.y, o[4 * i + 1]);
                    o[4 * i + 2] = fmaf(p, vv.z, o[4 * i + 2]);
                    o[4 * i + 3] = fmaf(p, vv.w, o[4 * i + 3]);
                }
            }
        }
    }

    const float inv = 1.0f / l;
    float* outp = g_ctx + qoff;
#pragma unroll
    for (int i = 0; i < 16; i++) {
        float4 t;
        t.x = o[4 * i + 0] * inv;
        t.y = o[4 * i + 1] * inv;
        t.z = o[4 * i + 2] * inv;
        t.w = o[4 * i + 3] * inv;
        *(float4*)(outp + i * 4) = t;
    }
}

// ---------------------------------------------------------------------------
extern "C" void kernel_launch(void* const* d_in, const int* in_sizes, int n_in,
                              void* d_out, int out_size)
{
    const float* query = (const float*)d_in[0];
    const float* key   = (const float*)d_in[1];
    const float* value = (const float*)d_in[2];
    const float* Wq    = (const float*)d_in[3];
    const float* bq    = (const float*)d_in[4];
    const float* Wk    = (const float*)d_in[5];
    const float* bk    = (const float*)d_in[6];
    const float* Wv    = (const float*)d_in[7];
    const float* bv    = (const float*)d_in[8];
    const float* Wo    = (const float*)d_in[9];
    const float* bo    = (const float*)d_in[10];

    float *qp, *kp, *vp, *cp;
    cudaGetSymbolAddress((void**)&qp, g_q);
    cudaGetSymbolAddress((void**)&kp, g_k);
    cudaGetSymbolAddress((void**)&vp, g_v);
    cudaGetSymbolAddress((void**)&cp, g_ctx);

    dim3 gemm_grid(DM / BN, MTOK / BM);   // (8, 32)
    gemm_nt_bias<<<gemm_grid, 256>>>(query, Wq, bq, qp, MTOK, DM, DM);
    gemm_nt_bias<<<gemm_grid, 256>>>(key,   Wk, bk, kp, MTOK, DM, DM);
    gemm_nt_bias<<<gemm_grid, 256>>>(value, Wv, bv, vp, MTOK, DM, DM);

    attn_kernel<<<dim3(SEQ / 128, NH, NB), 128>>>();

    gemm_nt_bias<<<gemm_grid, 256>>>(cp, Wo, bo, (float*)d_out, MTOK, DM, DM);
}